// round 1
// baseline (speedup 1.0000x reference)
#include <cuda_runtime.h>

constexpr int NMAX  = 100000;
constexpr int D_IN  = 16;
constexpr int D_HID = 32;
constexpr int D_OUT = 16;

// Scratch (allocation-free rule: __device__ globals). 16B-aligned for float4/red.v4.
__device__ alignas(16) float g_hs1 [NMAX * D_HID];
__device__ alignas(16) float g_agg1[NMAX * D_HID];
__device__ alignas(16) float g_hs2 [NMAX * D_OUT];
__device__ alignas(16) float g_agg2[NMAX * D_OUT];
__device__ float g_dinv[NMAX];
__device__ int   g_deg [NMAX];

// ---------------------------------------------------------------------------
// K0: zero accumulators + degree counters. Grid covers n*8 threads.
__global__ void k_zero(int n) {
    int i = blockIdx.x * blockDim.x + threadIdx.x;
    if (i < n * 8) reinterpret_cast<float4*>(g_agg1)[i] = make_float4(0.f, 0.f, 0.f, 0.f);
    if (i < n * 4) reinterpret_cast<float4*>(g_agg2)[i] = make_float4(0.f, 0.f, 0.f, 0.f);
    if (i < n)     g_deg[i] = 0;
}

// K1: degree count over real edges (self-loop folded in later as +1).
__global__ void k_deg(const int* __restrict__ dst, int E) {
    int i = blockIdx.x * blockDim.x + threadIdx.x;
    if (i < E) atomicAdd(&g_deg[dst[i]], 1);
}

// K2: per node: h = emb[x[v]]; hs1 = (h @ W1) * dinv[v]; store dinv.
__global__ void k_h1(const int* __restrict__ x, const float* __restrict__ emb,
                     const float* __restrict__ W1, int n) {
    __shared__ float W1s[D_IN * D_HID];
    for (int t = threadIdx.x; t < D_IN * D_HID; t += blockDim.x) W1s[t] = W1[t];
    __syncthreads();

    int v = blockIdx.x * blockDim.x + threadIdx.x;
    if (v >= n) return;

    int row = x[v];
    float h[D_IN];
    const float4* er = reinterpret_cast<const float4*>(emb + (size_t)row * D_IN);
#pragma unroll
    for (int q = 0; q < D_IN / 4; q++) {
        float4 t = er[q];
        h[q * 4 + 0] = t.x; h[q * 4 + 1] = t.y; h[q * 4 + 2] = t.z; h[q * 4 + 3] = t.w;
    }

    float acc[D_HID];
#pragma unroll
    for (int j = 0; j < D_HID; j++) acc[j] = 0.f;
#pragma unroll
    for (int k = 0; k < D_IN; k++) {
        float hv = h[k];
#pragma unroll
        for (int j = 0; j < D_HID; j++) acc[j] = fmaf(hv, W1s[k * D_HID + j], acc[j]);
    }

    float dinv = rsqrtf((float)(g_deg[v] + 1));  // +1 self-loop; deg >= 1 always
    g_dinv[v] = dinv;

    float4* o = reinterpret_cast<float4*>(g_hs1 + (size_t)v * D_HID);
#pragma unroll
    for (int q = 0; q < D_HID / 4; q++)
        o[q] = make_float4(acc[q * 4 + 0] * dinv, acc[q * 4 + 1] * dinv,
                           acc[q * 4 + 2] * dinv, acc[q * 4 + 3] * dinv);
}

// K3/K5: edge scatter. (1<<LOGF4) float4-chunks per edge; one thread per chunk.
// LAYER selects which global scratch buffers to use (device-symbol addressing
// must happen in device code).
template <int LAYER>
__global__ void k_scatter(const int* __restrict__ src, const int* __restrict__ dst,
                          int E) {
    constexpr int LOGF4 = (LAYER == 1) ? 3 : 2;           // 8 or 4 float4 per row
    const float* in  = (LAYER == 1) ? g_hs1  : g_hs2;
    float*       out = (LAYER == 1) ? g_agg1 : g_agg2;

    long long t = (long long)blockIdx.x * blockDim.x + threadIdx.x;
    int e = (int)(t >> LOGF4);
    if (e >= E) return;
    int c = (int)t & ((1 << LOGF4) - 1);

    int s = __ldg(&src[e]);
    int d = __ldg(&dst[e]);

    float4 v = *reinterpret_cast<const float4*>(in + ((size_t)s << (LOGF4 + 2)) + c * 4);
    float* p = out + ((size_t)d << (LOGF4 + 2)) + c * 4;
    asm volatile("red.global.add.v4.f32 [%0], {%1,%2,%3,%4};"
                 :: "l"(p), "f"(v.x), "f"(v.y), "f"(v.z), "f"(v.w) : "memory");
}

// K4: per node: r = relu(dinv*(agg1 + hs1) + b1); hs2 = (r @ W2) * dinv.
__global__ void k_post1(const float* __restrict__ b1, const float* __restrict__ W2,
                        int n) {
    __shared__ float W2s[D_HID * D_OUT];
    __shared__ float b1s[D_HID];
    for (int t = threadIdx.x; t < D_HID * D_OUT; t += blockDim.x) W2s[t] = W2[t];
    if (threadIdx.x < D_HID) b1s[threadIdx.x] = b1[threadIdx.x];
    __syncthreads();

    int v = blockIdx.x * blockDim.x + threadIdx.x;
    if (v >= n) return;

    float dinv = g_dinv[v];
    float r[D_HID];
    const float4* ar = reinterpret_cast<const float4*>(g_agg1 + (size_t)v * D_HID);
    const float4* hr = reinterpret_cast<const float4*>(g_hs1  + (size_t)v * D_HID);
#pragma unroll
    for (int q = 0; q < D_HID / 4; q++) {
        float4 a = ar[q], h = hr[q];
        r[q * 4 + 0] = fmaxf(dinv * (a.x + h.x) + b1s[q * 4 + 0], 0.f);
        r[q * 4 + 1] = fmaxf(dinv * (a.y + h.y) + b1s[q * 4 + 1], 0.f);
        r[q * 4 + 2] = fmaxf(dinv * (a.z + h.z) + b1s[q * 4 + 2], 0.f);
        r[q * 4 + 3] = fmaxf(dinv * (a.w + h.w) + b1s[q * 4 + 3], 0.f);
    }

    float acc[D_OUT];
#pragma unroll
    for (int j = 0; j < D_OUT; j++) acc[j] = 0.f;
#pragma unroll
    for (int k = 0; k < D_HID; k++) {
        float rv = r[k];
#pragma unroll
        for (int j = 0; j < D_OUT; j++) acc[j] = fmaf(rv, W2s[k * D_OUT + j], acc[j]);
    }

    float4* o = reinterpret_cast<float4*>(g_hs2 + (size_t)v * D_OUT);
#pragma unroll
    for (int q = 0; q < D_OUT / 4; q++)
        o[q] = make_float4(acc[q * 4 + 0] * dinv, acc[q * 4 + 1] * dinv,
                           acc[q * 4 + 2] * dinv, acc[q * 4 + 3] * dinv);
}

// K6: per node: out = dinv*(agg2 + hs2) + b2.
__global__ void k_post2(const float* __restrict__ b2, float* __restrict__ out, int n) {
    int v = blockIdx.x * blockDim.x + threadIdx.x;
    if (v >= n) return;
    float dinv = g_dinv[v];
    const float4* ar = reinterpret_cast<const float4*>(g_agg2 + (size_t)v * D_OUT);
    const float4* hr = reinterpret_cast<const float4*>(g_hs2  + (size_t)v * D_OUT);
    float4* o = reinterpret_cast<float4*>(out + (size_t)v * D_OUT);
#pragma unroll
    for (int q = 0; q < D_OUT / 4; q++) {
        float4 a = ar[q], h = hr[q];
        float bx = __ldg(&b2[q * 4 + 0]), by = __ldg(&b2[q * 4 + 1]);
        float bz = __ldg(&b2[q * 4 + 2]), bw = __ldg(&b2[q * 4 + 3]);
        o[q] = make_float4(dinv * (a.x + h.x) + bx, dinv * (a.y + h.y) + by,
                           dinv * (a.z + h.z) + bz, dinv * (a.w + h.w) + bw);
    }
}

extern "C" void kernel_launch(void* const* d_in, const int* in_sizes, int n_in,
                              void* d_out, int out_size) {
    const int*   x   = (const int*)  d_in[0];
    const int*   ei  = (const int*)  d_in[1];   // [2, E] row-major: src then dst
    const float* emb = (const float*)d_in[2];
    const float* W1  = (const float*)d_in[3];
    const float* b1  = (const float*)d_in[4];
    const float* W2  = (const float*)d_in[5];
    const float* b2  = (const float*)d_in[6];
    float* out = (float*)d_out;

    int n = in_sizes[0];
    int E = in_sizes[1] / 2;
    const int* src = ei;
    const int* dst = ei + E;

    const int B = 256;
    int nb_node = (n + B - 1) / B;

    k_zero<<<(n * 8 + B - 1) / B, B>>>(n);
    k_deg <<<(E + B - 1) / B, B>>>(dst, E);
    k_h1  <<<nb_node, B>>>(x, emb, W1, n);

    long long t1 = (long long)E * 8;
    k_scatter<1><<<(int)((t1 + B - 1) / B), B>>>(src, dst, E);

    k_post1<<<nb_node, B>>>(b1, W2, n);

    long long t2 = (long long)E * 4;
    k_scatter<2><<<(int)((t2 + B - 1) / B), B>>>(src, dst, E);

    k_post2<<<nb_node, B>>>(b2, out, n);
}

// round 2
// speedup vs baseline: 1.0218x; 1.0218x over previous
#include <cuda_runtime.h>

constexpr int NMAX  = 100000;
constexpr int EMAX  = 1600000;
constexpr int D_IN  = 16;
constexpr int D_HID = 32;
constexpr int D_OUT = 16;

// Scratch (__device__ globals; allocation-free rule).
__device__ alignas(16) float g_hs1[NMAX * D_HID];   // (emb@W1)*dinv
__device__ alignas(16) float g_r  [NMAX * D_HID];   // relu(conv1 out)
__device__ alignas(16) float g_hs2[NMAX * D_OUT];   // (r@W2)*dinv
__device__ float g_dinv[NMAX];
__device__ int   g_deg [NMAX];
__device__ int   g_row [NMAX];      // CSR row start (by dst)
__device__ int   g_cur [NMAX];      // fill cursor; after fill == row end
__device__ int   g_csr [EMAX];      // src node per CSR slot
__device__ int   g_csum[256];       // per-chunk sums for scan
__device__ int   g_coff[256];       // per-chunk exclusive offsets

// ---------------------------------------------------------------------------
__global__ void k_zero(int n) {
    int i = blockIdx.x * blockDim.x + threadIdx.x;
    if (i < n) g_deg[i] = 0;
}

// Degree histogram over real edges (self-loop added as +1 later).
__global__ void k_deg(const int* __restrict__ dst, int E) {
    int i = blockIdx.x * blockDim.x + threadIdx.x;
    int e4 = i * 4;
    if (e4 + 3 < E) {
        int4 d = *reinterpret_cast<const int4*>(dst + e4);
        atomicAdd(&g_deg[d.x], 1); atomicAdd(&g_deg[d.y], 1);
        atomicAdd(&g_deg[d.z], 1); atomicAdd(&g_deg[d.w], 1);
    } else {
        for (int e = e4; e < E; e++) atomicAdd(&g_deg[dst[e]], 1);
    }
}

// ---- 3-phase exclusive scan of g_deg -> g_row (chunk = 512 elems) ---------
__global__ void k_scan_a(int n) {
    int t = threadIdx.x;
    int i0 = blockIdx.x * 512 + 2 * t;
    int p = ((i0 < n) ? g_deg[i0] : 0) + ((i0 + 1 < n) ? g_deg[i0 + 1] : 0);
#pragma unroll
    for (int o = 16; o > 0; o >>= 1) p += __shfl_down_sync(~0u, p, o);
    __shared__ int ws[8];
    if ((t & 31) == 0) ws[t >> 5] = p;
    __syncthreads();
    if (t == 0) {
        int s = 0;
#pragma unroll
        for (int w = 0; w < 8; w++) s += ws[w];
        g_csum[blockIdx.x] = s;
    }
}

__global__ void k_scan_b(int nchunks) {
    __shared__ int sm[256];
    int t = threadIdx.x;
    int v = (t < nchunks) ? g_csum[t] : 0;
    sm[t] = v;
    __syncthreads();
#pragma unroll
    for (int o = 1; o < 256; o <<= 1) {
        int x = (t >= o) ? sm[t - o] : 0;
        __syncthreads();
        sm[t] += x;
        __syncthreads();
    }
    g_coff[t] = sm[t] - v;   // exclusive
}

__global__ void k_scan_c(int n) {
    int t = threadIdx.x, lane = t & 31, w = t >> 5;
    int i0 = blockIdx.x * 512 + 2 * t;
    int d0 = (i0 < n) ? g_deg[i0] : 0;
    int d1 = (i0 + 1 < n) ? g_deg[i0 + 1] : 0;
    int p = d0 + d1, incl = p;
#pragma unroll
    for (int o = 1; o < 32; o <<= 1) {
        int x = __shfl_up_sync(~0u, incl, o);
        if (lane >= o) incl += x;
    }
    __shared__ int ws[8];
    if (lane == 31) ws[w] = incl;
    __syncthreads();
    if (t == 0) {
        int run = 0;
#pragma unroll
        for (int i = 0; i < 8; i++) { int tmp = ws[i]; ws[i] = run; run += tmp; }
    }
    __syncthreads();
    int excl = incl - p + ws[w] + g_coff[blockIdx.x];
    if (i0 < n)     { g_row[i0] = excl;      g_cur[i0] = excl; }
    if (i0 + 1 < n) { g_row[i0 + 1] = excl + d0; g_cur[i0 + 1] = excl + d0; }
}

// Bucket fill: csr[pos] = src for each edge, bucketed by dst.
__global__ void k_fill(const int* __restrict__ src, const int* __restrict__ dst,
                       int E) {
    int e = blockIdx.x * blockDim.x + threadIdx.x;
    if (e >= E) return;
    int d = dst[e];
    int pos = atomicAdd(&g_cur[d], 1);
    g_csr[pos] = src[e];
}

// Per node: h = emb[x[v]]; hs1 = (h @ W1) * dinv; store dinv.
__global__ void k_h1(const int* __restrict__ x, const float* __restrict__ emb,
                     const float* __restrict__ W1, int n) {
    __shared__ float W1s[D_IN * D_HID];
    for (int t = threadIdx.x; t < D_IN * D_HID; t += blockDim.x) W1s[t] = W1[t];
    __syncthreads();
    int v = blockIdx.x * blockDim.x + threadIdx.x;
    if (v >= n) return;

    int row = x[v];
    float h[D_IN];
    const float4* er = reinterpret_cast<const float4*>(emb + (size_t)row * D_IN);
#pragma unroll
    for (int q = 0; q < D_IN / 4; q++) {
        float4 t = er[q];
        h[q*4+0] = t.x; h[q*4+1] = t.y; h[q*4+2] = t.z; h[q*4+3] = t.w;
    }
    float acc[D_HID];
#pragma unroll
    for (int j = 0; j < D_HID; j++) acc[j] = 0.f;
#pragma unroll
    for (int k = 0; k < D_IN; k++) {
        float hv = h[k];
#pragma unroll
        for (int j = 0; j < D_HID; j++) acc[j] = fmaf(hv, W1s[k * D_HID + j], acc[j]);
    }
    float dinv = rsqrtf((float)(g_deg[v] + 1));
    g_dinv[v] = dinv;
    float4* o = reinterpret_cast<float4*>(g_hs1 + (size_t)v * D_HID);
#pragma unroll
    for (int q = 0; q < D_HID / 4; q++)
        o[q] = make_float4(acc[q*4+0]*dinv, acc[q*4+1]*dinv,
                           acc[q*4+2]*dinv, acc[q*4+3]*dinv);
}

// Layer-1 aggregation: one warp per node; 4 neighbors/iter; epilogue = relu+b1.
__global__ void k_agg1(const float* __restrict__ b1, int n) {
    int gw = (blockIdx.x * blockDim.x + threadIdx.x) >> 5;
    if (gw >= n) return;
    int v = gw;
    int lane = threadIdx.x & 31;
    int chunk = lane & 7;      // which float4 of 8 (row = 32 floats)
    int sub   = lane >> 3;     // neighbor subgroup 0..3

    int start = g_row[v], end = g_cur[v];
    float4 acc = make_float4(0.f, 0.f, 0.f, 0.f);
    int j = start + sub;
    int s = (j < end) ? __ldg(&g_csr[j]) : 0;
    while (j < end) {
        int jn = j + 4;
        int sn = (jn < end) ? __ldg(&g_csr[jn]) : 0;
        float4 t = *reinterpret_cast<const float4*>(g_hs1 + ((size_t)s * D_HID) + chunk * 4);
        acc.x += t.x; acc.y += t.y; acc.z += t.z; acc.w += t.w;
        j = jn; s = sn;
    }
    // reduce over sub (lane bits 3,4)
#pragma unroll
    for (int o = 8; o <= 16; o <<= 1) {
        acc.x += __shfl_xor_sync(~0u, acc.x, o);
        acc.y += __shfl_xor_sync(~0u, acc.y, o);
        acc.z += __shfl_xor_sync(~0u, acc.z, o);
        acc.w += __shfl_xor_sync(~0u, acc.w, o);
    }
    if (sub == 0) {
        float4 self = *reinterpret_cast<const float4*>(g_hs1 + (size_t)v * D_HID + chunk * 4);
        float dinv = g_dinv[v];
        float4 bb = *reinterpret_cast<const float4*>(b1 + chunk * 4);
        float4 r;
        r.x = fmaxf(dinv * (acc.x + self.x) + bb.x, 0.f);
        r.y = fmaxf(dinv * (acc.y + self.y) + bb.y, 0.f);
        r.z = fmaxf(dinv * (acc.z + self.z) + bb.z, 0.f);
        r.w = fmaxf(dinv * (acc.w + self.w) + bb.w, 0.f);
        *reinterpret_cast<float4*>(g_r + (size_t)v * D_HID + chunk * 4) = r;
    }
}

// Per node: hs2 = (r @ W2) * dinv.
__global__ void k_lin2(const float* __restrict__ W2, int n) {
    __shared__ float W2s[D_HID * D_OUT];
    for (int t = threadIdx.x; t < D_HID * D_OUT; t += blockDim.x) W2s[t] = W2[t];
    __syncthreads();
    int v = blockIdx.x * blockDim.x + threadIdx.x;
    if (v >= n) return;
    float r[D_HID];
    const float4* rr = reinterpret_cast<const float4*>(g_r + (size_t)v * D_HID);
#pragma unroll
    for (int q = 0; q < D_HID / 4; q++) {
        float4 t = rr[q];
        r[q*4+0] = t.x; r[q*4+1] = t.y; r[q*4+2] = t.z; r[q*4+3] = t.w;
    }
    float acc[D_OUT];
#pragma unroll
    for (int j = 0; j < D_OUT; j++) acc[j] = 0.f;
#pragma unroll
    for (int k = 0; k < D_HID; k++) {
        float rv = r[k];
#pragma unroll
        for (int j = 0; j < D_OUT; j++) acc[j] = fmaf(rv, W2s[k * D_OUT + j], acc[j]);
    }
    float dinv = g_dinv[v];
    float4* o = reinterpret_cast<float4*>(g_hs2 + (size_t)v * D_OUT);
#pragma unroll
    for (int q = 0; q < D_OUT / 4; q++)
        o[q] = make_float4(acc[q*4+0]*dinv, acc[q*4+1]*dinv,
                           acc[q*4+2]*dinv, acc[q*4+3]*dinv);
}

// Layer-2 aggregation: one warp per node; 8 neighbors/iter; epilogue = +b2 -> out.
__global__ void k_agg2(const float* __restrict__ b2, float* __restrict__ out, int n) {
    int gw = (blockIdx.x * blockDim.x + threadIdx.x) >> 5;
    if (gw >= n) return;
    int v = gw;
    int lane = threadIdx.x & 31;
    int chunk = lane & 3;      // which float4 of 4 (row = 16 floats)
    int sub   = lane >> 2;     // neighbor subgroup 0..7

    int start = g_row[v], end = g_cur[v];
    float4 acc = make_float4(0.f, 0.f, 0.f, 0.f);
    int j = start + sub;
    int s = (j < end) ? __ldg(&g_csr[j]) : 0;
    while (j < end) {
        int jn = j + 8;
        int sn = (jn < end) ? __ldg(&g_csr[jn]) : 0;
        float4 t = *reinterpret_cast<const float4*>(g_hs2 + ((size_t)s * D_OUT) + chunk * 4);
        acc.x += t.x; acc.y += t.y; acc.z += t.z; acc.w += t.w;
        j = jn; s = sn;
    }
#pragma unroll
    for (int o = 4; o <= 16; o <<= 1) {
        acc.x += __shfl_xor_sync(~0u, acc.x, o);
        acc.y += __shfl_xor_sync(~0u, acc.y, o);
        acc.z += __shfl_xor_sync(~0u, acc.z, o);
        acc.w += __shfl_xor_sync(~0u, acc.w, o);
    }
    if (sub == 0) {
        float4 self = *reinterpret_cast<const float4*>(g_hs2 + (size_t)v * D_OUT + chunk * 4);
        float dinv = g_dinv[v];
        float4 bb = *reinterpret_cast<const float4*>(b2 + chunk * 4);
        float4 r;
        r.x = dinv * (acc.x + self.x) + bb.x;
        r.y = dinv * (acc.y + self.y) + bb.y;
        r.z = dinv * (acc.z + self.z) + bb.z;
        r.w = dinv * (acc.w + self.w) + bb.w;
        *reinterpret_cast<float4*>(out + (size_t)v * D_OUT + chunk * 4) = r;
    }
}

extern "C" void kernel_launch(void* const* d_in, const int* in_sizes, int n_in,
                              void* d_out, int out_size) {
    const int*   x   = (const int*)  d_in[0];
    const int*   ei  = (const int*)  d_in[1];   // [2, E]: src then dst
    const float* emb = (const float*)d_in[2];
    const float* W1  = (const float*)d_in[3];
    const float* b1  = (const float*)d_in[4];
    const float* W2  = (const float*)d_in[5];
    const float* b2  = (const float*)d_in[6];
    float* out = (float*)d_out;

    int n = in_sizes[0];
    int E = in_sizes[1] / 2;
    const int* src = ei;
    const int* dst = ei + E;

    const int B = 256;
    int nb_node  = (n + B - 1) / B;
    int nchunks  = (n + 511) / 512;

    k_zero  <<<nb_node, B>>>(n);
    k_deg   <<<(E / 4 + B - 1) / B + 1, B>>>(dst, E);
    k_h1    <<<nb_node, B>>>(x, emb, W1, n);
    k_scan_a<<<nchunks, 256>>>(n);
    k_scan_b<<<1, 256>>>(nchunks);
    k_scan_c<<<nchunks, 256>>>(n);
    k_fill  <<<(E + B - 1) / B, B>>>(src, dst, E);

    int warp_threads = n * 32;
    k_agg1  <<<(warp_threads + B - 1) / B, B>>>(b1, n);
    k_lin2  <<<nb_node, B>>>(W2, n);
    k_agg2  <<<(warp_threads + B - 1) / B, B>>>(b2, out, n);
}